// round 16
// baseline (speedup 1.0000x reference)
#include <cuda_runtime.h>
#include <cuda.h>
#include <cstdint>

static constexpr int DIM   = 8;
static constexpr int PATCH = 16;
static constexpr int NPAIR = PATCH - 1;
static constexpr int W     = 2 * DIM;

typedef unsigned long long u64;

__device__ __forceinline__ u64 pack2(float lo, float hi) {
    u64 r;
    asm("mov.b64 %0, {%1, %2};" : "=l"(r) : "f"(lo), "f"(hi));
    return r;
}
__device__ __forceinline__ u64 fma2(u64 a, u64 b, u64 c) {
    u64 d;
    asm("fma.rn.f32x2 %0, %1, %2, %3;" : "=l"(d) : "l"(a), "l"(b), "l"(c));
    return d;
}
__device__ __forceinline__ uint32_t smem_u32(const void* p) {
    uint32_t a;
    asm("{ .reg .u64 t; cvta.to.shared.u64 t, %1; cvt.u32.u64 %0, t; }"
        : "=r"(a) : "l"(p));
    return a;
}

// Thread t: p = t>>3 (0..15, warp-uniform half), q = t&7. Thread owns cells
// A=(p,q) and C=(p,q+8); both share s1 = S1[p], da = d[p&7], db = d[q].
// Scalar Chen chain; v-accumulators in packed f32x2.
template <bool AL>
__device__ __forceinline__ void mainloop(
    const float (*__restrict__ sd)[DIM],
    int pl, int q,
    float& s1, float& s2A, float& s2C,
    u64* __restrict__ vA,
    u64* __restrict__ vC)
{
    #pragma unroll
    for (int k = 0; k < NPAIR; k++) {
        const ulonglong2* sdv = reinterpret_cast<const ulonglong2*>(sd[k]);
        const ulonglong2 dA = sdv[0];
        const ulonglong2 dB = sdv[1];
        const float da = sd[k][pl];
        const float db = sd[k][q];

        float coefAL, coefAG, coefCL, coefCG;
        if (AL) {
            // p<8: p active in LEAD. Cell A (b=q) in LEAD, C (b=q+8) in LAG.
            float tt = da * db;
            float pa = s1 * db;
            coefAL = fmaf(0.5f, pa, s2A);
            coefAL = fmaf(1.0f / 6.0f, tt, coefAL);
            coefCL = s2C;
            s2A    = s2A + pa;
            s2A    = fmaf(0.5f, tt, s2A);
            s1    += da;
            float pc = pa + tt;           // (s1+da)*db == pa + tt
            coefAG = s2A;
            coefCG = fmaf(0.5f, pc, s2C);
            s2C   += pc;
        } else {
            // p>=8: p active in LAG; s1 unchanged until lag => pc == pa.
            float pa = s1 * db;
            coefAL = fmaf(0.5f, pa, s2A);
            coefCL = s2C;
            s2A   += pa;
            coefAG = s2A;
            float tt = da * db;
            coefCG = fmaf(0.5f, pa, s2C);
            coefCG = fmaf(1.0f / 6.0f, tt, coefCG);
            s2C   += pa;
            s2C    = fmaf(0.5f, tt, s2C);
            s1    += da;
        }

        const u64 cAL = pack2(coefAL, coefAL);
        const u64 cAG = pack2(coefAG, coefAG);
        const u64 cCL = pack2(coefCL, coefCL);
        const u64 cCG = pack2(coefCG, coefCG);

        vA[0] = fma2(cAL, dA.x, vA[0]);  vA[1] = fma2(cAL, dA.y, vA[1]);
        vA[2] = fma2(cAL, dB.x, vA[2]);  vA[3] = fma2(cAL, dB.y, vA[3]);
        vA[4] = fma2(cAG, dA.x, vA[4]);  vA[5] = fma2(cAG, dA.y, vA[5]);
        vA[6] = fma2(cAG, dB.x, vA[6]);  vA[7] = fma2(cAG, dB.y, vA[7]);

        vC[0] = fma2(cCL, dA.x, vC[0]);  vC[1] = fma2(cCL, dA.y, vC[1]);
        vC[2] = fma2(cCL, dB.x, vC[2]);  vC[3] = fma2(cCL, dB.y, vC[3]);
        vC[4] = fma2(cCG, dA.x, vC[4]);  vC[5] = fma2(cCG, dA.y, vC[5]);
        vC[6] = fma2(cCG, dB.x, vC[6]);  vC[7] = fma2(cCG, dB.y, vC[7]);
    }
}

// 16B-chunk swizzle == TMA SW128 layout for a 128B-wide tile. Restricted to
// any 1024B-aligned sub-region it equals the local-tile swizzle, so per-warp
// 4KB regions are valid standalone SW128 tiles.
__device__ __forceinline__ int swz(int c) {
    return c ^ ((c >> 3) & 7);
}

__global__ __launch_bounds__(128, 8)
void leadlag_sig_kernel(const float* __restrict__ x,
                        float* __restrict__ out,
                        int seq_len,
                        const __grid_constant__ CUtensorMap dmap)
{
    const int i = blockIdx.x;
    const int t = threadIdx.x;       // 0..127
    const int w = t >> 5;            // warp
    const int l = t & 31;            // lane
    const int p = t >> 3;            // first index 0..15 (warp-uniform half)
    const int q = t & 7;             // second index low part

    __shared__ __align__(16)   float sd[4][NPAIR][DIM];  // per-warp deltas
    __shared__ __align__(16)   float s1buf[16];
    __shared__ __align__(16)   float s2buf[256];
    __shared__ __align__(1024) ulonglong2 sbuf[1024];    // 16 KB SW128 tile

    // ---- per-warp delta load: lane m<30 produces float4 #m ----
    if (l < 30) {
        int k  = l >> 1;
        int h  = (l & 1) << 2;
        int g1 = i + k - (PATCH - 2);
        int g0 = i + k - (PATCH - 1);
        float4 v1 = (g1 >= 0) ? *reinterpret_cast<const float4*>(x + g1 * DIM + h)
                              : make_float4(0.f, 0.f, 0.f, 0.f);
        float4 v0 = (g0 >= 0) ? *reinterpret_cast<const float4*>(x + g0 * DIM + h)
                              : make_float4(0.f, 0.f, 0.f, 0.f);
        *reinterpret_cast<float4*>(&sd[w][k][h]) =
            make_float4(v1.x - v0.x, v1.y - v0.y, v1.z - v0.z, v1.w - v0.w);
    }
    __syncwarp();

    float s1 = 0.0f, s2A = 0.0f, s2C = 0.0f;
    u64 vA[8], vC[8];
    #pragma unroll
    for (int j = 0; j < 8; j++) { vA[j] = 0ull; vC[j] = 0ull; }

    const int pl = p & 7;
    if (p < 8) mainloop<true >(sd[w], pl, q, s1, s2A, s2C, vA, vC);
    else       mainloop<false>(sd[w], pl, q, s1, s2A, s2C, vA, vC);

    // ---- stage level-3 rows into SW128-swizzled smem (warp-local region) ----
    {
        const int rA = p * W + q;        // row of cell (p, q)
        const int rC = rA + 8;           // row of cell (p, q+8)
        #pragma unroll
        for (int s = 0; s < 4; s++) {
            sbuf[swz(4 * rA + s)] = make_ulonglong2(vA[2 * s], vA[2 * s + 1]);
            sbuf[swz(4 * rC + s)] = make_ulonglong2(vC[2 * s], vC[2 * s + 1]);
        }
    }

    // ---- stage level-1 / level-2 (warp-local slices) ----
    if (q == 0) s1buf[p] = s1;
    s2buf[p * W + q]     = s2A;
    s2buf[p * W + q + 8] = s2C;

    __syncwarp();

    // ---- per-warp async epilogue: no block barrier anywhere ----
    if (l == 0) {
        asm volatile("fence.proxy.async.shared::cta;" ::: "memory");
        float* out1 = out + (size_t)i * W + 4 * w;
        float* out2 = out + (size_t)seq_len * W + (size_t)i * (W * W) + 64 * w;
        uint32_t sa3 = smem_u32(sbuf) + 4096u * w;      // warp's 4KB tile
        uint32_t sa2 = smem_u32(s2buf) + 256u * w;
        uint32_t sa1 = smem_u32(s1buf) + 16u * w;
        asm volatile(
            "cp.async.bulk.tensor.3d.global.shared::cta.tile.bulk_group "
            "[%0, {%1, %2, %3}], [%4];"
            :: "l"(&dmap), "r"(0), "r"(32 * w), "r"(i), "r"(sa3)
            : "memory");
        asm volatile(
            "cp.async.bulk.global.shared::cta.bulk_group [%0], [%1], %2;"
            :: "l"(out2), "r"(sa2), "n"(64 * 4)
            : "memory");
        asm volatile(
            "cp.async.bulk.global.shared::cta.bulk_group [%0], [%1], %2;"
            :: "l"(out1), "r"(sa1), "n"(4 * 4)
            : "memory");
        asm volatile("cp.async.bulk.commit_group;" ::: "memory");
        // Only smem-read completion is needed before CTA exit/smem reuse.
        asm volatile("cp.async.bulk.wait_group.read 0;" ::: "memory");
    }
}

extern "C" void kernel_launch(void* const* d_in, const int* in_sizes, int n_in,
                              void* d_out, int out_size)
{
    const float* x   = (const float*)d_in[0];
    float*       out = (float*)d_out;
    const int seq_len = in_sizes[0] / DIM;   // 8192

    // L3 region: seq_len tiles of 128 TMA-rows x 32 f32 (128B), contiguous.
    float* out3 = out + (size_t)seq_len * (W + W * W);

    typedef CUresult (*EncodeFn)(
        CUtensorMap*, CUtensorMapDataType, cuuint32_t, void*,
        const cuuint64_t*, const cuuint64_t*, const cuuint32_t*,
        const cuuint32_t*, CUtensorMapInterleave, CUtensorMapSwizzle,
        CUtensorMapL2promotion, CUtensorMapFloatOOBfill);
    static EncodeFn encode = nullptr;
    if (!encode) {
        cudaDriverEntryPointQueryResult st;
        void* fn = nullptr;
        cudaGetDriverEntryPoint("cuTensorMapEncodeTiled", &fn,
                                cudaEnableDefault, &st);
        encode = (EncodeFn)fn;
    }

    CUtensorMap dmap;
    cuuint64_t dims[3]    = {32, 128, (cuuint64_t)seq_len};
    cuuint64_t strides[2] = {128, 16384};          // bytes
    cuuint32_t box[3]     = {32, 32, 1};           // per-warp 4KB slab
    cuuint32_t estr[3]    = {1, 1, 1};
    encode(&dmap, CU_TENSOR_MAP_DATA_TYPE_FLOAT32, 3, (void*)out3,
           dims, strides, box, estr,
           CU_TENSOR_MAP_INTERLEAVE_NONE, CU_TENSOR_MAP_SWIZZLE_128B,
           CU_TENSOR_MAP_L2_PROMOTION_L2_128B,
           CU_TENSOR_MAP_FLOAT_OOB_FILL_NONE);

    leadlag_sig_kernel<<<seq_len, 128>>>(x, out, seq_len, dmap);
}

// round 17
// speedup vs baseline: 1.0272x; 1.0272x over previous
#include <cuda_runtime.h>
#include <cuda.h>
#include <cstdint>

static constexpr int DIM   = 8;
static constexpr int PATCH = 16;
static constexpr int NPAIR = PATCH - 1;
static constexpr int W     = 2 * DIM;

typedef unsigned long long u64;

__device__ __forceinline__ u64 pack2(float lo, float hi) {
    u64 r;
    asm("mov.b64 %0, {%1, %2};" : "=l"(r) : "f"(lo), "f"(hi));
    return r;
}
__device__ __forceinline__ u64 fma2(u64 a, u64 b, u64 c) {
    u64 d;
    asm("fma.rn.f32x2 %0, %1, %2, %3;" : "=l"(d) : "l"(a), "l"(b), "l"(c));
    return d;
}
__device__ __forceinline__ uint32_t smem_u32(const void* p) {
    uint32_t a;
    asm("{ .reg .u64 t; cvta.to.shared.u64 t, %1; cvt.u32.u64 %0, t; }"
        : "=r"(a) : "l"(p));
    return a;
}

// Thread t: p = t>>3 (0..15, warp-uniform half), q = t&7. Thread owns cells
// A=(p,q) and C=(p,q+8); both share s1 = S1[p], da = d[p&7], db = d[q].
// Scalar Chen chain; v-accumulators in packed f32x2. Coef->update sequencing
// per cell keeps peak live registers low (56-reg target).
template <bool AL>
__device__ __forceinline__ void mainloop(
    const float (*__restrict__ sd)[DIM],
    int pl, int q,
    float& s1, float& s2A, float& s2C,
    u64* __restrict__ vA,
    u64* __restrict__ vC)
{
    #pragma unroll
    for (int k = 0; k < NPAIR; k++) {
        const ulonglong2* sdv = reinterpret_cast<const ulonglong2*>(sd[k]);
        const ulonglong2 dA = sdv[0];
        const ulonglong2 dB = sdv[1];
        const float da = sd[k][pl];
        const float db = sd[k][q];

        float tt = da * db;
        float pa = s1 * db;

        // ---- cell A: coefs then immediate accumulator update ----
        {
            float coefAL, coefAG;
            if (AL) {
                coefAL = fmaf(0.5f, pa, s2A);
                coefAL = fmaf(1.0f / 6.0f, tt, coefAL);
                s2A    = s2A + pa;
                s2A    = fmaf(0.5f, tt, s2A);
                coefAG = s2A;
            } else {
                coefAL = fmaf(0.5f, pa, s2A);
                s2A   += pa;
                coefAG = s2A;
            }
            const u64 cAL = pack2(coefAL, coefAL);
            const u64 cAG = pack2(coefAG, coefAG);
            vA[0] = fma2(cAL, dA.x, vA[0]);  vA[1] = fma2(cAL, dA.y, vA[1]);
            vA[2] = fma2(cAL, dB.x, vA[2]);  vA[3] = fma2(cAL, dB.y, vA[3]);
            vA[4] = fma2(cAG, dA.x, vA[4]);  vA[5] = fma2(cAG, dA.y, vA[5]);
            vA[6] = fma2(cAG, dB.x, vA[6]);  vA[7] = fma2(cAG, dB.y, vA[7]);
        }

        // ---- cell C: coefs then immediate accumulator update ----
        {
            float coefCL, coefCG;
            if (AL) {
                // lead trivial for C; lag uses pc = (s1+da)*db = pa + tt
                coefCL = s2C;
                float pc = pa + tt;
                coefCG = fmaf(0.5f, pc, s2C);
                s2C   += pc;
            } else {
                // lead trivial; lag full (pc == pa since s1 not yet updated)
                coefCL = s2C;
                coefCG = fmaf(0.5f, pa, s2C);
                coefCG = fmaf(1.0f / 6.0f, tt, coefCG);
                s2C   += pa;
                s2C    = fmaf(0.5f, tt, s2C);
            }
            const u64 cCL = pack2(coefCL, coefCL);
            const u64 cCG = pack2(coefCG, coefCG);
            vC[0] = fma2(cCL, dA.x, vC[0]);  vC[1] = fma2(cCL, dA.y, vC[1]);
            vC[2] = fma2(cCL, dB.x, vC[2]);  vC[3] = fma2(cCL, dB.y, vC[3]);
            vC[4] = fma2(cCG, dA.x, vC[4]);  vC[5] = fma2(cCG, dA.y, vC[5]);
            vC[6] = fma2(cCG, dB.x, vC[6]);  vC[7] = fma2(cCG, dB.y, vC[7]);
        }

        s1 += da;   // same final value in both branches; ordering-safe since
                    // all pa/pc terms above use the k-step-correct s1 values
    }
}

// 16B-chunk swizzle == TMA SW128 layout for a 128B-wide tile.
__device__ __forceinline__ int swz(int c) {
    return c ^ ((c >> 3) & 7);
}

__global__ __launch_bounds__(128, 9)
void leadlag_sig_kernel(const float* __restrict__ x,
                        float* __restrict__ out,
                        int seq_len,
                        const __grid_constant__ CUtensorMap dmap)
{
    const int i = blockIdx.x;
    const int t = threadIdx.x;       // 0..127
    const int p = t >> 3;            // first index 0..15 (warp-uniform half)
    const int q = t & 7;             // second index low part

    __shared__ __align__(16)   float sd[NPAIR][DIM];
    __shared__ __align__(16)   float s1buf[16];       // L1 staging (64 B)
    __shared__ __align__(16)   float s2buf[256];      // L2 staging (1 KB)
    __shared__ __align__(1024) ulonglong2 sbuf[1024]; // 16 KB SW128 L3 tile

    if (t < NPAIR * DIM) {
        int k  = t >> 3;
        int c  = t & 7;
        int g1 = i + k - (PATCH - 2);
        int g0 = i + k - (PATCH - 1);
        float v1 = (g1 >= 0) ? x[g1 * DIM + c] : 0.0f;
        float v0 = (g0 >= 0) ? x[g0 * DIM + c] : 0.0f;
        sd[k][c] = v1 - v0;
    }
    __syncthreads();

    float s1 = 0.0f, s2A = 0.0f, s2C = 0.0f;
    u64 vA[8], vC[8];
    #pragma unroll
    for (int j = 0; j < 8; j++) { vA[j] = 0ull; vC[j] = 0ull; }

    const int pl = p & 7;
    if (p < 8) mainloop<true >(sd, pl, q, s1, s2A, s2C, vA, vC);
    else       mainloop<false>(sd, pl, q, s1, s2A, s2C, vA, vC);

    // ---- stage level-3 rows into SW128-swizzled smem ----
    {
        const int rA = p * W + q;        // row of cell (p, q)
        const int rC = rA + 8;           // row of cell (p, q+8)
        #pragma unroll
        for (int s = 0; s < 4; s++) {
            sbuf[swz(4 * rA + s)] = make_ulonglong2(vA[2 * s], vA[2 * s + 1]);
            sbuf[swz(4 * rC + s)] = make_ulonglong2(vC[2 * s], vC[2 * s + 1]);
        }
    }

    // ---- stage level-1 / level-2 into smem ----
    if (q == 0) s1buf[p] = s1;
    s2buf[p * W + q]     = s2A;
    s2buf[p * W + q + 8] = s2C;

    __syncthreads();

    // ---- async bulk epilogue: L3 tensor store + L2/L1 1D bulk copies ----
    if (t == 0) {
        asm volatile("fence.proxy.async.shared::cta;" ::: "memory");
        float* out1 = out + (size_t)i * W;
        float* out2 = out + (size_t)seq_len * W + (size_t)i * (W * W);
        uint32_t sa3 = smem_u32(sbuf);
        uint32_t sa2 = smem_u32(s2buf);
        uint32_t sa1 = smem_u32(s1buf);
        asm volatile(
            "cp.async.bulk.tensor.3d.global.shared::cta.tile.bulk_group "
            "[%0, {%1, %2, %3}], [%4];"
            :: "l"(&dmap), "r"(0), "r"(0), "r"(i), "r"(sa3)
            : "memory");
        asm volatile(
            "cp.async.bulk.global.shared::cta.bulk_group [%0], [%1], %2;"
            :: "l"(out2), "r"(sa2), "n"(W * W * 4)
            : "memory");
        asm volatile(
            "cp.async.bulk.global.shared::cta.bulk_group [%0], [%1], %2;"
            :: "l"(out1), "r"(sa1), "n"(W * 4)
            : "memory");
        asm volatile("cp.async.bulk.commit_group;" ::: "memory");
        asm volatile("cp.async.bulk.wait_group.read 0;" ::: "memory");
    }
}

extern "C" void kernel_launch(void* const* d_in, const int* in_sizes, int n_in,
                              void* d_out, int out_size)
{
    const float* x   = (const float*)d_in[0];
    float*       out = (float*)d_out;
    const int seq_len = in_sizes[0] / DIM;   // 8192

    // L3 region: seq_len tiles of 128 rows x 32 f32 (128B wide), contiguous.
    float* out3 = out + (size_t)seq_len * (W + W * W);

    typedef CUresult (*EncodeFn)(
        CUtensorMap*, CUtensorMapDataType, cuuint32_t, void*,
        const cuuint64_t*, const cuuint64_t*, const cuuint32_t*,
        const cuuint32_t*, CUtensorMapInterleave, CUtensorMapSwizzle,
        CUtensorMapL2promotion, CUtensorMapFloatOOBfill);
    static EncodeFn encode = nullptr;
    if (!encode) {
        cudaDriverEntryPointQueryResult st;
        void* fn = nullptr;
        cudaGetDriverEntryPoint("cuTensorMapEncodeTiled", &fn,
                                cudaEnableDefault, &st);
        encode = (EncodeFn)fn;
    }

    CUtensorMap dmap;
    cuuint64_t dims[3]    = {32, 128, (cuuint64_t)seq_len};
    cuuint64_t strides[2] = {128, 16384};          // bytes
    cuuint32_t box[3]     = {32, 128, 1};
    cuuint32_t estr[3]    = {1, 1, 1};
    encode(&dmap, CU_TENSOR_MAP_DATA_TYPE_FLOAT32, 3, (void*)out3,
           dims, strides, box, estr,
           CU_TENSOR_MAP_INTERLEAVE_NONE, CU_TENSOR_MAP_SWIZZLE_128B,
           CU_TENSOR_MAP_L2_PROMOTION_L2_128B,
           CU_TENSOR_MAP_FLOAT_OOB_FILL_NONE);

    leadlag_sig_kernel<<<seq_len, 128>>>(x, out, seq_len, dmap);
}